// round 2
// baseline (speedup 1.0000x reference)
#include <cuda_runtime.h>
#include <cstdint>
#include <cstddef>

// Problem dims
#define Bn 4096
#define Dn 256
#define Hn 2048
#define On 256

static constexpr size_t BH      = (size_t)Bn * Hn;          // 8,388,608
static constexpr size_t SE2_OFF = (size_t)8 * Bn * On;      // task_out elems = 8,388,608
static constexpr size_t SE3_OFF = SE2_OFF + (size_t)4 * BH; // + 33,554,432

// Scratch: per-task hidden activations (te), 8 * 4096 * 2048 fp32 = 256 MB (.bss, no alloc)
__device__ float g_te[(size_t)8 * Bn * Hn];
// Gates for all 18 experts: [18, B]
__device__ float g_gate[18 * Bn];

// Routing: which expert contributions feed each task output
__constant__ int c_cnt[8]    = {1, 3, 2, 2, 4, 2, 2, 2};
__constant__ int c_lst[8][4] = {
    {0, 0, 0, 0},
    {1, 8, 9, 0},
    {2, 10, 0, 0},
    {3, 11, 0, 0},
    {4, 12, 13, 14},
    {5, 15, 0, 0},
    {6, 16, 0, 0},
    {7, 17, 0, 0}
};

struct P {
    const float* x[8];
    const float* W_task; const float* b_task; const float* Wg_task; const float* bg_task;
    const float* Wo_task; const float* bo_task;
    const float* W_b2;  const float* b_b2;  const float* Wg_b2;  const float* bg_b2;
    const float* Wo_b2; const float* bo_b2;
    const float* W_b3;  const float* b_b3;  const float* Wg_b3;  const float* bg_b3;
    const float* Wo_b3; const float* bo_b3;
    float* out;
};

// ============================================================================
// Kernel 1: hidden = relu(X_e @ W_e + b_e) for 18 experts.
//   e 0..7  : task experts, K=256, A = x[e],             dst = g_te[e]
//   e 8..11 : b2 experts,   K=512, A = [x2 | x3],        dst = out + SE2
//   e 12..17: b3 experts,   K=768, A = [x5 | x6 | x7],   dst = out + SE3
// Tile 128x128x8, 256 threads, 8x8 microtile.
// ============================================================================
__global__ __launch_bounds__(256) void k_hidden(P p) {
    const int e = blockIdx.z;
    const float* xp0; const float* xp1 = nullptr; const float* xp2 = nullptr;
    int K; const float* W; const float* bias; float* dst;
    if (e < 8) {
        K = 256; xp0 = p.x[e];
        W = p.W_task + (size_t)e * Dn * Hn;
        bias = p.b_task + e * Hn;
        dst = g_te + (size_t)e * BH;
    } else if (e < 12) {
        const int q = e - 8;
        K = 512; xp0 = p.x[2]; xp1 = p.x[3];
        W = p.W_b2 + (size_t)q * 512 * Hn;
        bias = p.b_b2 + q * Hn;
        dst = p.out + SE2_OFF + (size_t)q * BH;
    } else {
        const int q = e - 12;
        K = 768; xp0 = p.x[5]; xp1 = p.x[6]; xp2 = p.x[7];
        W = p.W_b3 + (size_t)q * 768 * Hn;
        bias = p.b_b3 + q * Hn;
        dst = p.out + SE3_OFF + (size_t)q * BH;
    }

    __shared__ float As[8][128];
    __shared__ float Bs[8][128];

    const int tid = threadIdx.x;
    const int tx = tid & 15, ty = tid >> 4;
    const int row0 = blockIdx.y * 128, col0 = blockIdx.x * 128;
    const int a_row = tid >> 1, a_k4 = (tid & 1) * 4;
    const int b_k = tid >> 5,  b_n  = (tid & 31) * 4;

    float acc[8][8];
#pragma unroll
    for (int i = 0; i < 8; i++)
#pragma unroll
        for (int j = 0; j < 8; j++) acc[i][j] = 0.f;

    for (int k0 = 0; k0 < K; k0 += 8) {
        const int gk = k0 + a_k4;
        const int part = gk >> 8;
        const float* xa = (part == 0) ? xp0 : ((part == 1) ? xp1 : xp2);
        const float4 av = *(const float4*)(xa + (size_t)(row0 + a_row) * Dn + (gk & 255));
        As[a_k4 + 0][a_row] = av.x;
        As[a_k4 + 1][a_row] = av.y;
        As[a_k4 + 2][a_row] = av.z;
        As[a_k4 + 3][a_row] = av.w;
        const float4 bv = *(const float4*)(W + (size_t)(k0 + b_k) * Hn + col0 + b_n);
        *(float4*)(&Bs[b_k][b_n]) = bv;
        __syncthreads();
#pragma unroll
        for (int kk = 0; kk < 8; kk++) {
            float a[8], b[8];
            *(float4*)(a)     = *(const float4*)(&As[kk][ty * 4]);
            *(float4*)(a + 4) = *(const float4*)(&As[kk][ty * 4 + 64]);
            *(float4*)(b)     = *(const float4*)(&Bs[kk][tx * 4]);
            *(float4*)(b + 4) = *(const float4*)(&Bs[kk][tx * 4 + 64]);
#pragma unroll
            for (int i = 0; i < 8; i++)
#pragma unroll
                for (int j = 0; j < 8; j++)
                    acc[i][j] = fmaf(a[i], b[j], acc[i][j]);
        }
        __syncthreads();
    }

    // Epilogue: bias + relu, store
#pragma unroll
    for (int i = 0; i < 8; i++) {
        const int r = row0 + ((i < 4) ? (ty * 4 + i) : (64 + ty * 4 + (i - 4)));
#pragma unroll
        for (int jh = 0; jh < 2; jh++) {
            const int c = col0 + tx * 4 + jh * 64;
            float4 o;
            o.x = fmaxf(acc[i][jh * 4 + 0] + bias[c + 0], 0.f);
            o.y = fmaxf(acc[i][jh * 4 + 1] + bias[c + 1], 0.f);
            o.z = fmaxf(acc[i][jh * 4 + 2] + bias[c + 2], 0.f);
            o.w = fmaxf(acc[i][jh * 4 + 3] + bias[c + 3], 0.f);
            *(float4*)(&dst[(size_t)r * Hn + c]) = o;
        }
    }
}

// ============================================================================
// Kernel 2: gates.
//   e 0..7  : gt = sigmoid(x[e] . Wg_task[e] + bg)   (K=256, on the INPUT)
//   e 8..11 : g2 = sigmoid(se2 . Wg_b2 + bg)          (K=2048, on the hidden)
//   e 12..17: g3 = sigmoid(se3 . Wg_b3 + bg)
// One 128-thread block per (expert, row).
// ============================================================================
__global__ __launch_bounds__(128) void k_gate(P p) {
    const int e = blockIdx.y;
    const int row = blockIdx.x;
    const float* src; const float* wg; float bg; int K;
    if (e < 8) {
        src = p.x[e] + (size_t)row * Dn;
        wg = p.Wg_task + e * Dn; bg = p.bg_task[e]; K = Dn;
    } else if (e < 12) {
        const int q = e - 8;
        src = p.out + SE2_OFF + (size_t)q * BH + (size_t)row * Hn;
        wg = p.Wg_b2 + q * Hn; bg = p.bg_b2[q]; K = Hn;
    } else {
        const int q = e - 12;
        src = p.out + SE3_OFF + (size_t)q * BH + (size_t)row * Hn;
        wg = p.Wg_b3 + q * Hn; bg = p.bg_b3[q]; K = Hn;
    }
    float s = 0.f;
    for (int i = threadIdx.x; i < K; i += 128) s += src[i] * wg[i];
    __shared__ float red[128];
    red[threadIdx.x] = s;
    __syncthreads();
#pragma unroll
    for (int o = 64; o > 0; o >>= 1) {
        if (threadIdx.x < o) red[threadIdx.x] += red[threadIdx.x + o];
        __syncthreads();
    }
    if (threadIdx.x == 0)
        g_gate[e * Bn + row] = 1.f / (1.f + expf(-(red[0] + bg)));
}

// ============================================================================
// Kernel 3: task_out[t] = sum_{e in list(t)} (g_e (.) hid_e) @ Wo_e + bo_e
// Tile 128x128x8, accumulate all routed contributions in one CTA (no atomics).
// Gate applied as per-row scale on A while staging into smem.
// ============================================================================
__global__ __launch_bounds__(256) void k_out(P p) {
    const int t = blockIdx.z;
    const int row0 = blockIdx.y * 128, col0 = blockIdx.x * 128;

    __shared__ float As[8][128];
    __shared__ float Bs[8][128];
    __shared__ float gs[128];

    const int tid = threadIdx.x;
    const int tx = tid & 15, ty = tid >> 4;
    const int a_row = tid >> 1, a_k4 = (tid & 1) * 4;
    const int b_k = tid >> 5,  b_n  = (tid & 31) * 4;

    float acc[8][8];
#pragma unroll
    for (int i = 0; i < 8; i++)
#pragma unroll
        for (int j = 0; j < 8; j++) acc[i][j] = 0.f;

    const int nc = c_cnt[t];
    for (int ci = 0; ci < nc; ci++) {
        const int e = c_lst[t][ci];
        const float* hid; const float* Wo;
        if (e < 8) {
            hid = g_te + (size_t)e * BH;
            Wo = p.Wo_task + (size_t)e * Hn * On;
        } else if (e < 12) {
            hid = p.out + SE2_OFF + (size_t)(e - 8) * BH;
            Wo = p.Wo_b2 + (size_t)(e - 8) * Hn * On;
        } else {
            hid = p.out + SE3_OFF + (size_t)(e - 12) * BH;
            Wo = p.Wo_b3 + (size_t)(e - 12) * Hn * On;
        }
        if (tid < 128) gs[tid] = g_gate[e * Bn + row0 + tid];
        __syncthreads();

        for (int k0 = 0; k0 < Hn; k0 += 8) {
            const float g = gs[a_row];
            const float4 av = *(const float4*)(hid + (size_t)(row0 + a_row) * Hn + k0 + a_k4);
            As[a_k4 + 0][a_row] = av.x * g;
            As[a_k4 + 1][a_row] = av.y * g;
            As[a_k4 + 2][a_row] = av.z * g;
            As[a_k4 + 3][a_row] = av.w * g;
            const float4 bv = *(const float4*)(Wo + (size_t)(k0 + b_k) * On + col0 + b_n);
            *(float4*)(&Bs[b_k][b_n]) = bv;
            __syncthreads();
#pragma unroll
            for (int kk = 0; kk < 8; kk++) {
                float a[8], b[8];
                *(float4*)(a)     = *(const float4*)(&As[kk][ty * 4]);
                *(float4*)(a + 4) = *(const float4*)(&As[kk][ty * 4 + 64]);
                *(float4*)(b)     = *(const float4*)(&Bs[kk][tx * 4]);
                *(float4*)(b + 4) = *(const float4*)(&Bs[kk][tx * 4 + 64]);
#pragma unroll
                for (int i = 0; i < 8; i++)
#pragma unroll
                    for (int j = 0; j < 8; j++)
                        acc[i][j] = fmaf(a[i], b[j], acc[i][j]);
            }
            __syncthreads();
        }
    }

    // Epilogue: add summed biases of all contributions, write task_out
#pragma unroll
    for (int i = 0; i < 8; i++) {
        const int r = row0 + ((i < 4) ? (ty * 4 + i) : (64 + ty * 4 + (i - 4)));
#pragma unroll
        for (int jh = 0; jh < 2; jh++) {
            const int c = col0 + tx * 4 + jh * 64;
            float4 o;
            o.x = acc[i][jh * 4 + 0];
            o.y = acc[i][jh * 4 + 1];
            o.z = acc[i][jh * 4 + 2];
            o.w = acc[i][jh * 4 + 3];
            for (int ci = 0; ci < nc; ci++) {
                const int e = c_lst[t][ci];
                const float* bo = (e < 8) ? (p.bo_task + e * On)
                                 : (e < 12) ? (p.bo_b2 + (e - 8) * On)
                                            : (p.bo_b3 + (e - 12) * On);
                o.x += bo[c + 0]; o.y += bo[c + 1]; o.z += bo[c + 2]; o.w += bo[c + 3];
            }
            *(float4*)(&p.out[(size_t)t * Bn * On + (size_t)r * On + c]) = o;
        }
    }
}

// ============================================================================
extern "C" void kernel_launch(void* const* d_in, const int* in_sizes, int n_in,
                              void* d_out, int out_size) {
    P p;
    for (int i = 0; i < 8; i++) p.x[i] = (const float*)d_in[i];
    p.W_task  = (const float*)d_in[8];
    p.b_task  = (const float*)d_in[9];
    p.Wg_task = (const float*)d_in[10];
    p.bg_task = (const float*)d_in[11];
    p.Wo_task = (const float*)d_in[12];
    p.bo_task = (const float*)d_in[13];
    p.W_b2    = (const float*)d_in[14];
    p.b_b2    = (const float*)d_in[15];
    p.Wg_b2   = (const float*)d_in[16];
    p.bg_b2   = (const float*)d_in[17];
    p.Wo_b2   = (const float*)d_in[18];
    p.bo_b2   = (const float*)d_in[19];
    p.W_b3    = (const float*)d_in[20];
    p.b_b3    = (const float*)d_in[21];
    p.Wg_b3   = (const float*)d_in[22];
    p.bg_b3   = (const float*)d_in[23];
    p.Wo_b3   = (const float*)d_in[24];
    p.bo_b3   = (const float*)d_in[25];
    p.out = (float*)d_out;

    dim3 g1(Hn / 128, Bn / 128, 18);   // 16 x 32 x 18 = 9216 CTAs
    k_hidden<<<g1, 256>>>(p);

    dim3 g2(Bn, 18);                   // 73728 small blocks
    k_gate<<<g2, 128>>>(p);

    dim3 g3(On / 128, Bn / 128, 8);    // 2 x 32 x 8 = 512 CTAs
    k_out<<<g3, 256>>>(p);
}

// round 3
// speedup vs baseline: 1.0027x; 1.0027x over previous
#include <cuda_runtime.h>
#include <cstdint>
#include <cstddef>

// Problem dims
#define Bn 4096
#define Dn 256
#define Hn 2048
#define On 256

static constexpr size_t BH      = (size_t)Bn * Hn;          // 8,388,608
static constexpr size_t SE2_OFF = (size_t)8 * Bn * On;      // task_out elems = 8,388,608
static constexpr size_t SE3_OFF = SE2_OFF + (size_t)4 * BH; // + 33,554,432

// Scratch: per-task hidden activations (te), 8 * 4096 * 2048 fp32 = 256 MB (.bss, no alloc)
__device__ float g_te[(size_t)8 * Bn * Hn];
// Gates for all 18 experts: [18, B]
__device__ float g_gate[18 * Bn];

// Routing: which expert contributions feed each task output
__constant__ int c_cnt[8]    = {1, 3, 2, 2, 4, 2, 2, 2};
__constant__ int c_lst[8][4] = {
    {0, 0, 0, 0},
    {1, 8, 9, 0},
    {2, 10, 0, 0},
    {3, 11, 0, 0},
    {4, 12, 13, 14},
    {5, 15, 0, 0},
    {6, 16, 0, 0},
    {7, 17, 0, 0}
};

struct P {
    const float* x[8];
    const float* W_task; const float* b_task; const float* Wg_task; const float* bg_task;
    const float* Wo_task; const float* bo_task;
    const float* W_b2;  const float* b_b2;  const float* Wg_b2;  const float* bg_b2;
    const float* Wo_b2; const float* bo_b2;
    const float* W_b3;  const float* b_b3;  const float* Wg_b3;  const float* bg_b3;
    const float* Wo_b3; const float* bo_b3;
    float* out;
};

// ============================================================================
// Kernel 1: hidden = relu(X_e @ W_e + b_e) for 18 experts.
//   e 0..7  : task experts, K=256, A = x[e],             dst = g_te[e]
//   e 8..11 : b2 experts,   K=512, A = [x2 | x3],        dst = out + SE2
//   e 12..17: b3 experts,   K=768, A = [x5 | x6 | x7],   dst = out + SE3
// Tile 128x128x8, 256 threads, 8x8 microtile.
// ============================================================================
__global__ __launch_bounds__(256) void k_hidden(P p) {
    const int e = blockIdx.z;
    const float* xp0; const float* xp1 = nullptr; const float* xp2 = nullptr;
    int K; const float* W; const float* bias; float* dst;
    if (e < 8) {
        K = 256; xp0 = p.x[e];
        W = p.W_task + (size_t)e * Dn * Hn;
        bias = p.b_task + e * Hn;
        dst = g_te + (size_t)e * BH;
    } else if (e < 12) {
        const int q = e - 8;
        K = 512; xp0 = p.x[2]; xp1 = p.x[3];
        W = p.W_b2 + (size_t)q * 512 * Hn;
        bias = p.b_b2 + q * Hn;
        dst = p.out + SE2_OFF + (size_t)q * BH;
    } else {
        const int q = e - 12;
        K = 768; xp0 = p.x[5]; xp1 = p.x[6]; xp2 = p.x[7];
        W = p.W_b3 + (size_t)q * 768 * Hn;
        bias = p.b_b3 + q * Hn;
        dst = p.out + SE3_OFF + (size_t)q * BH;
    }

    __shared__ float As[8][128];
    __shared__ float Bs[8][128];

    const int tid = threadIdx.x;
    const int tx = tid & 15, ty = tid >> 4;
    const int row0 = blockIdx.y * 128, col0 = blockIdx.x * 128;
    const int a_row = tid >> 1, a_k4 = (tid & 1) * 4;
    const int b_k = tid >> 5,  b_n  = (tid & 31) * 4;

    float acc[8][8];
#pragma unroll
    for (int i = 0; i < 8; i++)
#pragma unroll
        for (int j = 0; j < 8; j++) acc[i][j] = 0.f;

    for (int k0 = 0; k0 < K; k0 += 8) {
        const int gk = k0 + a_k4;
        const int part = gk >> 8;
        const float* xa = (part == 0) ? xp0 : ((part == 1) ? xp1 : xp2);
        const float4 av = *(const float4*)(xa + (size_t)(row0 + a_row) * Dn + (gk & 255));
        As[a_k4 + 0][a_row] = av.x;
        As[a_k4 + 1][a_row] = av.y;
        As[a_k4 + 2][a_row] = av.z;
        As[a_k4 + 3][a_row] = av.w;
        const float4 bv = *(const float4*)(W + (size_t)(k0 + b_k) * Hn + col0 + b_n);
        *(float4*)(&Bs[b_k][b_n]) = bv;
        __syncthreads();
#pragma unroll
        for (int kk = 0; kk < 8; kk++) {
            float a[8], b[8];
            *(float4*)(a)     = *(const float4*)(&As[kk][ty * 4]);
            *(float4*)(a + 4) = *(const float4*)(&As[kk][ty * 4 + 64]);
            *(float4*)(b)     = *(const float4*)(&Bs[kk][tx * 4]);
            *(float4*)(b + 4) = *(const float4*)(&Bs[kk][tx * 4 + 64]);
#pragma unroll
            for (int i = 0; i < 8; i++)
#pragma unroll
                for (int j = 0; j < 8; j++)
                    acc[i][j] = fmaf(a[i], b[j], acc[i][j]);
        }
        __syncthreads();
    }

    // Epilogue: bias + relu, store
#pragma unroll
    for (int i = 0; i < 8; i++) {
        const int r = row0 + ((i < 4) ? (ty * 4 + i) : (64 + ty * 4 + (i - 4)));
#pragma unroll
        for (int jh = 0; jh < 2; jh++) {
            const int c = col0 + tx * 4 + jh * 64;
            float4 o;
            o.x = fmaxf(acc[i][jh * 4 + 0] + bias[c + 0], 0.f);
            o.y = fmaxf(acc[i][jh * 4 + 1] + bias[c + 1], 0.f);
            o.z = fmaxf(acc[i][jh * 4 + 2] + bias[c + 2], 0.f);
            o.w = fmaxf(acc[i][jh * 4 + 3] + bias[c + 3], 0.f);
            *(float4*)(&dst[(size_t)r * Hn + c]) = o;
        }
    }
}

// ============================================================================
// Kernel 2: gates.
//   e 0..7  : gt = sigmoid(x[e] . Wg_task[e] + bg)   (K=256, on the INPUT)
//   e 8..11 : g2 = sigmoid(se2 . Wg_b2 + bg)          (K=2048, on the hidden)
//   e 12..17: g3 = sigmoid(se3 . Wg_b3 + bg)
// One 128-thread block per (expert, row).
// ============================================================================
__global__ __launch_bounds__(128) void k_gate(P p) {
    const int e = blockIdx.y;
    const int row = blockIdx.x;
    const float* src; const float* wg; float bg; int K;
    if (e < 8) {
        src = p.x[e] + (size_t)row * Dn;
        wg = p.Wg_task + e * Dn; bg = p.bg_task[e]; K = Dn;
    } else if (e < 12) {
        const int q = e - 8;
        src = p.out + SE2_OFF + (size_t)q * BH + (size_t)row * Hn;
        wg = p.Wg_b2 + q * Hn; bg = p.bg_b2[q]; K = Hn;
    } else {
        const int q = e - 12;
        src = p.out + SE3_OFF + (size_t)q * BH + (size_t)row * Hn;
        wg = p.Wg_b3 + q * Hn; bg = p.bg_b3[q]; K = Hn;
    }
    float s = 0.f;
    for (int i = threadIdx.x; i < K; i += 128) s += src[i] * wg[i];
    __shared__ float red[128];
    red[threadIdx.x] = s;
    __syncthreads();
#pragma unroll
    for (int o = 64; o > 0; o >>= 1) {
        if (threadIdx.x < o) red[threadIdx.x] += red[threadIdx.x + o];
        __syncthreads();
    }
    if (threadIdx.x == 0)
        g_gate[e * Bn + row] = 1.f / (1.f + expf(-(red[0] + bg)));
}

// ============================================================================
// Kernel 3: task_out[t] = sum_{e in list(t)} (g_e (.) hid_e) @ Wo_e + bo_e
// Tile 128x128x8, accumulate all routed contributions in one CTA (no atomics).
// Gate applied as per-row scale on A while staging into smem.
// ============================================================================
__global__ __launch_bounds__(256) void k_out(P p) {
    const int t = blockIdx.z;
    const int row0 = blockIdx.y * 128, col0 = blockIdx.x * 128;

    __shared__ float As[8][128];
    __shared__ float Bs[8][128];
    __shared__ float gs[128];

    const int tid = threadIdx.x;
    const int tx = tid & 15, ty = tid >> 4;
    const int a_row = tid >> 1, a_k4 = (tid & 1) * 4;
    const int b_k = tid >> 5,  b_n  = (tid & 31) * 4;

    float acc[8][8];
#pragma unroll
    for (int i = 0; i < 8; i++)
#pragma unroll
        for (int j = 0; j < 8; j++) acc[i][j] = 0.f;

    const int nc = c_cnt[t];
    for (int ci = 0; ci < nc; ci++) {
        const int e = c_lst[t][ci];
        const float* hid; const float* Wo;
        if (e < 8) {
            hid = g_te + (size_t)e * BH;
            Wo = p.Wo_task + (size_t)e * Hn * On;
        } else if (e < 12) {
            hid = p.out + SE2_OFF + (size_t)(e - 8) * BH;
            Wo = p.Wo_b2 + (size_t)(e - 8) * Hn * On;
        } else {
            hid = p.out + SE3_OFF + (size_t)(e - 12) * BH;
            Wo = p.Wo_b3 + (size_t)(e - 12) * Hn * On;
        }
        if (tid < 128) gs[tid] = g_gate[e * Bn + row0 + tid];
        __syncthreads();

        for (int k0 = 0; k0 < Hn; k0 += 8) {
            const float g = gs[a_row];
            const float4 av = *(const float4*)(hid + (size_t)(row0 + a_row) * Hn + k0 + a_k4);
            As[a_k4 + 0][a_row] = av.x * g;
            As[a_k4 + 1][a_row] = av.y * g;
            As[a_k4 + 2][a_row] = av.z * g;
            As[a_k4 + 3][a_row] = av.w * g;
            const float4 bv = *(const float4*)(Wo + (size_t)(k0 + b_k) * On + col0 + b_n);
            *(float4*)(&Bs[b_k][b_n]) = bv;
            __syncthreads();
#pragma unroll
            for (int kk = 0; kk < 8; kk++) {
                float a[8], b[8];
                *(float4*)(a)     = *(const float4*)(&As[kk][ty * 4]);
                *(float4*)(a + 4) = *(const float4*)(&As[kk][ty * 4 + 64]);
                *(float4*)(b)     = *(const float4*)(&Bs[kk][tx * 4]);
                *(float4*)(b + 4) = *(const float4*)(&Bs[kk][tx * 4 + 64]);
#pragma unroll
                for (int i = 0; i < 8; i++)
#pragma unroll
                    for (int j = 0; j < 8; j++)
                        acc[i][j] = fmaf(a[i], b[j], acc[i][j]);
            }
            __syncthreads();
        }
    }

    // Epilogue: add summed biases of all contributions, write task_out
#pragma unroll
    for (int i = 0; i < 8; i++) {
        const int r = row0 + ((i < 4) ? (ty * 4 + i) : (64 + ty * 4 + (i - 4)));
#pragma unroll
        for (int jh = 0; jh < 2; jh++) {
            const int c = col0 + tx * 4 + jh * 64;
            float4 o;
            o.x = acc[i][jh * 4 + 0];
            o.y = acc[i][jh * 4 + 1];
            o.z = acc[i][jh * 4 + 2];
            o.w = acc[i][jh * 4 + 3];
            for (int ci = 0; ci < nc; ci++) {
                const int e = c_lst[t][ci];
                const float* bo = (e < 8) ? (p.bo_task + e * On)
                                 : (e < 12) ? (p.bo_b2 + (e - 8) * On)
                                            : (p.bo_b3 + (e - 12) * On);
                o.x += bo[c + 0]; o.y += bo[c + 1]; o.z += bo[c + 2]; o.w += bo[c + 3];
            }
            *(float4*)(&p.out[(size_t)t * Bn * On + (size_t)r * On + c]) = o;
        }
    }
}

// ============================================================================
extern "C" void kernel_launch(void* const* d_in, const int* in_sizes, int n_in,
                              void* d_out, int out_size) {
    P p;
    for (int i = 0; i < 8; i++) p.x[i] = (const float*)d_in[i];
    p.W_task  = (const float*)d_in[8];
    p.b_task  = (const float*)d_in[9];
    p.Wg_task = (const float*)d_in[10];
    p.bg_task = (const float*)d_in[11];
    p.Wo_task = (const float*)d_in[12];
    p.bo_task = (const float*)d_in[13];
    p.W_b2    = (const float*)d_in[14];
    p.b_b2    = (const float*)d_in[15];
    p.Wg_b2   = (const float*)d_in[16];
    p.bg_b2   = (const float*)d_in[17];
    p.Wo_b2   = (const float*)d_in[18];
    p.bo_b2   = (const float*)d_in[19];
    p.W_b3    = (const float*)d_in[20];
    p.b_b3    = (const float*)d_in[21];
    p.Wg_b3   = (const float*)d_in[22];
    p.bg_b3   = (const float*)d_in[23];
    p.Wo_b3   = (const float*)d_in[24];
    p.bo_b3   = (const float*)d_in[25];
    p.out = (float*)d_out;

    dim3 g1(Hn / 128, Bn / 128, 18);   // 16 x 32 x 18 = 9216 CTAs
    k_hidden<<<g1, 256>>>(p);

    dim3 g2(Bn, 18);                   // 73728 small blocks
    k_gate<<<g2, 128>>>(p);

    dim3 g3(On / 128, Bn / 128, 8);    // 2 x 32 x 8 = 512 CTAs
    k_out<<<g3, 256>>>(p);
}

// round 5
// speedup vs baseline: 2.5610x; 2.5541x over previous
#include <cuda_runtime.h>
#include <cstdint>
#include <cstddef>

// Problem dims
#define Bn 4096
#define Dn 256
#define Hn 2048
#define On 256

static constexpr size_t BH      = (size_t)Bn * Hn;
static constexpr size_t SE2_OFF = (size_t)8 * Bn * On;
static constexpr size_t SE3_OFF = SE2_OFF + (size_t)4 * BH;

// Scratch (.bss — no allocation)
__device__ float g_te[(size_t)8 * BH];       // per-task hidden, 256 MB
__device__ float g_gate[18 * Bn];

// Transposed tf32-rounded weights: [N,K] K-major rows
static constexpr size_t WT_TASK = 0;                                   // 8  x [2048 x 256]
static constexpr size_t WT_B2   = (size_t)8 * 2048 * 256;              // 4  x [2048 x 512]
static constexpr size_t WT_B3   = WT_B2 + (size_t)4 * 2048 * 512;      // 6  x [2048 x 768]
static constexpr size_t WOT     = WT_B3 + (size_t)6 * 2048 * 768;      // 18 x [256 x 2048]
__device__ float g_wt[WOT + (size_t)18 * 256 * 2048];

// Routing
__constant__ int c_cnt[8]    = {1, 3, 2, 2, 4, 2, 2, 2};
__constant__ int c_lst[8][4] = {
    {0,0,0,0},{1,8,9,0},{2,10,0,0},{3,11,0,0},
    {4,12,13,14},{5,15,0,0},{6,16,0,0},{7,17,0,0}
};

struct P {
    const float* x[8];
    const float* W_task; const float* b_task; const float* Wg_task; const float* bg_task;
    const float* Wo_task; const float* bo_task;
    const float* W_b2;  const float* b_b2;  const float* Wg_b2;  const float* bg_b2;
    const float* Wo_b2; const float* bo_b2;
    const float* W_b3;  const float* b_b3;  const float* Wg_b3;  const float* bg_b3;
    const float* Wo_b3; const float* bo_b3;
    float* out;
};

// ===================== helpers =====================
__device__ __forceinline__ uint32_t tf32u(float x) {
    uint32_t u; asm("cvt.rna.tf32.f32 %0, %1;" : "=r"(u) : "f"(x)); return u;
}
__device__ __forceinline__ uint32_t smem_u32(const void* p) {
    uint32_t a;
    asm("{ .reg .u64 t; cvta.to.shared.u64 t, %1; cvt.u32.u64 %0, t; }" : "=r"(a) : "l"(p));
    return a;
}
#define CP_ASYNC16(dst_u32, src_gptr) \
    asm volatile("cp.async.cg.shared.global [%0], [%1], 16;" :: "r"(dst_u32), "l"(src_gptr))
#define CP_COMMIT() asm volatile("cp.async.commit_group;" ::: "memory")
#define CP_WAIT0()  asm volatile("cp.async.wait_group 0;"  ::: "memory")

#define MMA8(d, a, b) \
    asm volatile("mma.sync.aligned.m16n8k8.row.col.f32.tf32.tf32.f32 " \
                 "{%0,%1,%2,%3}, {%4,%5,%6,%7}, {%8,%9}, {%0,%1,%2,%3};" \
                 : "+f"((d)[0]), "+f"((d)[1]), "+f"((d)[2]), "+f"((d)[3]) \
                 : "r"((a)[0]), "r"((a)[1]), "r"((a)[2]), "r"((a)[3]), \
                   "r"((b)[0]), "r"((b)[1]))

// Smem chunk buffers: stride 36 floats per 32-col row (pad for conflict-free frags)
#define TSTRIDE 36
#define BUFSZ   (128 * TSTRIDE)           // floats per buffer = 4608 (18432 B)
#define SMEM_DYN_BYTES (4 * BUFSZ * 4)    // A0,A1,B0,B1 = 73728 B

// ===================== Kernel 0: weight transpose + tf32 RNA round =====================
__global__ __launch_bounds__(256) void k_tr(const float* in, size_t off, int R, int C) {
    __shared__ float tile[32][33];
    const int z = blockIdx.z;
    const float* inz = in + (size_t)z * R * C;
    float* outz = g_wt + off + (size_t)z * R * C;
    const int rb = blockIdx.y * 32, cb = blockIdx.x * 32;
    const int tx = threadIdx.x, ty = threadIdx.y;
#pragma unroll
    for (int i = ty; i < 32; i += 8)
        tile[i][tx] = inz[(size_t)(rb + i) * C + cb + tx];
    __syncthreads();
#pragma unroll
    for (int i = ty; i < 32; i += 8)
        outz[(size_t)(cb + i) * R + rb + tx] = __uint_as_float(tf32u(tile[tx][i]));
}

// ===================== Kernel 1: hidden = relu(X_e @ W_e + b_e) =====================
// grid (Hn/128, Bn/128, 18), 256 threads, CTA tile 128x128x32, warp tile 64x32
__global__ __launch_bounds__(256, 2) void k_hidden_mma(P p) {
    extern __shared__ float sm[];
    float* As[2] = { sm,             sm + BUFSZ     };
    float* Bs[2] = { sm + 2 * BUFSZ, sm + 3 * BUFSZ };

    const int tid = threadIdx.x, wid = tid >> 5, lane = tid & 31;
    const int warp_m = wid >> 2, warp_n = wid & 3;   // 2 x 4
    const int g = lane >> 2, t = lane & 3;
    const int e = blockIdx.z;
    const int row0 = blockIdx.y * 128, n0 = blockIdx.x * 128;

    const float *xp0, *xp1 = nullptr, *xp2 = nullptr, *bias;
    const float* wt; int K; float* dst;
    if (e < 8) {
        K = 256; xp0 = p.x[e];
        wt = g_wt + WT_TASK + (size_t)e * Hn * 256;
        bias = p.b_task + e * Hn;
        dst = g_te + (size_t)e * BH;
    } else if (e < 12) {
        const int q = e - 8;
        K = 512; xp0 = p.x[2]; xp1 = p.x[3];
        wt = g_wt + WT_B2 + (size_t)q * Hn * 512;
        bias = p.b_b2 + q * Hn;
        dst = p.out + SE2_OFF + (size_t)q * BH;
    } else {
        const int q = e - 12;
        K = 768; xp0 = p.x[5]; xp1 = p.x[6]; xp2 = p.x[7];
        wt = g_wt + WT_B3 + (size_t)q * Hn * 768;
        bias = p.b_b3 + q * Hn;
        dst = p.out + SE3_OFF + (size_t)q * BH;
    }

    const int arow = tid >> 3, acol4 = (tid & 7) * 4;   // staging coords
    float acc[4][4][4];
#pragma unroll
    for (int m = 0; m < 4; m++)
#pragma unroll
        for (int n = 0; n < 4; n++)
#pragma unroll
            for (int r = 0; r < 4; r++) acc[m][n][r] = 0.f;

    float4 pa[4];
    // --- staging lambdas ---
    auto LDGA = [&](int kc) {
        const int kcol = kc * 32;
        const int part = kcol >> 8, kloc = (kcol & 255) + acol4;
        const float* xa = (part == 0) ? xp0 : ((part == 1) ? xp1 : xp2);
#pragma unroll
        for (int i = 0; i < 4; i++)
            pa[i] = *(const float4*)(xa + (size_t)(row0 + arow + i * 32) * Dn + kloc);
    };
    auto STSA = [&](int s) {
        float* ab = As[s];
#pragma unroll
        for (int i = 0; i < 4; i++) {
            uint4 w;
            w.x = tf32u(pa[i].x); w.y = tf32u(pa[i].y);
            w.z = tf32u(pa[i].z); w.w = tf32u(pa[i].w);
            *(uint4*)(ab + (arow + i * 32) * TSTRIDE + acol4) = w;
        }
    };
    auto CPB = [&](int kc, int s) {
        const int kcol = kc * 32;
        const uint32_t bb = smem_u32(Bs[s]);
#pragma unroll
        for (int i = 0; i < 4; i++) {
            const float* src = wt + (size_t)(n0 + arow + i * 32) * K + kcol + acol4;
            CP_ASYNC16(bb + ((arow + i * 32) * TSTRIDE + acol4) * 4, src);
        }
    };
    auto COMPUTE = [&](int s) {
        const uint32_t* Ab = (const uint32_t*)As[s];
        const uint32_t* Bb = (const uint32_t*)Bs[s];
#pragma unroll
        for (int kt = 0; kt < 4; kt++) {
            uint32_t af[4][4], bf[4][2];
#pragma unroll
            for (int m = 0; m < 4; m++) {
                const int base = (warp_m * 64 + m * 16 + g) * TSTRIDE + kt * 8 + t;
                af[m][0] = Ab[base];
                af[m][1] = Ab[base + 8 * TSTRIDE];
                af[m][2] = Ab[base + 4];
                af[m][3] = Ab[base + 8 * TSTRIDE + 4];
            }
#pragma unroll
            for (int n = 0; n < 4; n++) {
                const int base = (warp_n * 32 + n * 8 + g) * TSTRIDE + kt * 8 + t;
                bf[n][0] = Bb[base];
                bf[n][1] = Bb[base + 4];
            }
#pragma unroll
            for (int m = 0; m < 4; m++)
#pragma unroll
                for (int n = 0; n < 4; n++) MMA8(acc[m][n], af[m], bf[n]);
        }
    };

    const int KC = K / 32;
    // prologue
    LDGA(0); STSA(0);
    CPB(0, 0); CP_COMMIT(); CP_WAIT0();
    __syncthreads();
    for (int kc = 0; kc < KC; kc++) {
        const int s = kc & 1;
        const bool more = (kc + 1 < KC);
        if (more) LDGA(kc + 1);
        COMPUTE(s);
        if (more) {
            __syncthreads();
            CPB(kc + 1, s ^ 1); CP_COMMIT();
            STSA(s ^ 1);
            CP_WAIT0();
            __syncthreads();
        }
    }

    // epilogue: bias + relu
#pragma unroll
    for (int m = 0; m < 4; m++) {
        const int row = row0 + warp_m * 64 + m * 16 + g;
#pragma unroll
        for (int n = 0; n < 4; n++) {
            const int col = n0 + warp_n * 32 + n * 8 + 2 * t;
            const float b0 = bias[col], b1 = bias[col + 1];
            float2 v;
            v.x = fmaxf(acc[m][n][0] + b0, 0.f);
            v.y = fmaxf(acc[m][n][1] + b1, 0.f);
            *(float2*)(dst + (size_t)row * Hn + col) = v;
            v.x = fmaxf(acc[m][n][2] + b0, 0.f);
            v.y = fmaxf(acc[m][n][3] + b1, 0.f);
            *(float2*)(dst + (size_t)(row + 8) * Hn + col) = v;
        }
    }
}

// ===================== Kernel 2: gates (SIMT) =====================
__global__ __launch_bounds__(128) void k_gate(P p) {
    const int e = blockIdx.y;
    const int row = blockIdx.x;
    const float* src; const float* wg; float bg; int K;
    if (e < 8) {
        src = p.x[e] + (size_t)row * Dn;
        wg = p.Wg_task + e * Dn; bg = p.bg_task[e]; K = Dn;
    } else if (e < 12) {
        const int q = e - 8;
        src = p.out + SE2_OFF + (size_t)q * BH + (size_t)row * Hn;
        wg = p.Wg_b2 + q * Hn; bg = p.bg_b2[q]; K = Hn;
    } else {
        const int q = e - 12;
        src = p.out + SE3_OFF + (size_t)q * BH + (size_t)row * Hn;
        wg = p.Wg_b3 + q * Hn; bg = p.bg_b3[q]; K = Hn;
    }
    float s = 0.f;
    for (int i = threadIdx.x; i < K; i += 128) s += src[i] * wg[i];
    __shared__ float red[128];
    red[threadIdx.x] = s;
    __syncthreads();
#pragma unroll
    for (int o = 64; o > 0; o >>= 1) {
        if (threadIdx.x < o) red[threadIdx.x] += red[threadIdx.x + o];
        __syncthreads();
    }
    if (threadIdx.x == 0)
        g_gate[e * Bn + row] = 1.f / (1.f + expf(-(red[0] + bg)));
}

// ===================== Kernel 3: task_out, routed accumulation =====================
// grid (On/128, Bn/128, 8), 256 threads. Gate folded into A staging; acc persists
// across contributions.
__global__ __launch_bounds__(256, 2) void k_out_mma(P p) {
    extern __shared__ float sm[];
    float* As[2] = { sm,             sm + BUFSZ     };
    float* Bs[2] = { sm + 2 * BUFSZ, sm + 3 * BUFSZ };
    __shared__ float gs[4][128];
    __shared__ float bsum[128];

    const int tid = threadIdx.x, wid = tid >> 5, lane = tid & 31;
    const int warp_m = wid >> 2, warp_n = wid & 3;
    const int g = lane >> 2, t = lane & 3;
    const int tk = blockIdx.z;
    const int row0 = blockIdx.y * 128, n0 = blockIdx.x * 128;
    const int nc = c_cnt[tk];

    // Resolve contribution sources
    const float* hid[4]; const float* wb[4];
    for (int ci = 0; ci < nc; ci++) {
        const int e = c_lst[tk][ci];
        hid[ci] = (e < 8) ? g_te + (size_t)e * BH
                : (e < 12) ? p.out + SE2_OFF + (size_t)(e - 8) * BH
                           : p.out + SE3_OFF + (size_t)(e - 12) * BH;
        wb[ci] = g_wt + WOT + (size_t)e * On * Hn;
    }
    if (tid < 128) {
        float s = 0.f;
        for (int ci = 0; ci < nc; ci++) {
            const int e = c_lst[tk][ci];
            gs[ci][tid] = g_gate[e * Bn + row0 + tid];
            const float* bo = (e < 8) ? (p.bo_task + e * On)
                             : (e < 12) ? (p.bo_b2 + (e - 8) * On)
                                        : (p.bo_b3 + (e - 12) * On);
            s += bo[n0 + tid];
        }
        bsum[tid] = s;
    }
    __syncthreads();

    const int arow = tid >> 3, acol4 = (tid & 7) * 4;
    float acc[4][4][4];
#pragma unroll
    for (int m = 0; m < 4; m++)
#pragma unroll
        for (int n = 0; n < 4; n++)
#pragma unroll
            for (int r = 0; r < 4; r++) acc[m][n][r] = 0.f;

    float4 pa[4];
    auto LDGA = [&](int kc) {
        const int ci = kc >> 6, kcol = (kc & 63) * 32;
#pragma unroll
        for (int i = 0; i < 4; i++)
            pa[i] = *(const float4*)(hid[ci] + (size_t)(row0 + arow + i * 32) * Hn + kcol + acol4);
    };
    auto STSA = [&](int kc, int s) {
        const int ci = kc >> 6;
        float* ab = As[s];
#pragma unroll
        for (int i = 0; i < 4; i++) {
            const float gv = gs[ci][arow + i * 32];
            uint4 w;
            w.x = tf32u(pa[i].x * gv); w.y = tf32u(pa[i].y * gv);
            w.z = tf32u(pa[i].z * gv); w.w = tf32u(pa[i].w * gv);
            *(uint4*)(ab + (arow + i * 32) * TSTRIDE + acol4) = w;
        }
    };
    auto CPB = [&](int kc, int s) {
        const int ci = kc >> 6, kcol = (kc & 63) * 32;
        const uint32_t bb = smem_u32(Bs[s]);
#pragma unroll
        for (int i = 0; i < 4; i++) {
            const float* src = wb[ci] + (size_t)(n0 + arow + i * 32) * Hn + kcol + acol4;
            CP_ASYNC16(bb + ((arow + i * 32) * TSTRIDE + acol4) * 4, src);
        }
    };
    auto COMPUTE = [&](int s) {
        const uint32_t* Ab = (const uint32_t*)As[s];
        const uint32_t* Bb = (const uint32_t*)Bs[s];
#pragma unroll
        for (int kt = 0; kt < 4; kt++) {
            uint32_t af[4][4], bf[4][2];
#pragma unroll
            for (int m = 0; m < 4; m++) {
                const int base = (warp_m * 64 + m * 16 + g) * TSTRIDE + kt * 8 + t;
                af[m][0] = Ab[base];
                af[m][1] = Ab[base + 8 * TSTRIDE];
                af[m][2] = Ab[base + 4];
                af[m][3] = Ab[base + 8 * TSTRIDE + 4];
            }
#pragma unroll
            for (int n = 0; n < 4; n++) {
                const int base = (warp_n * 32 + n * 8 + g) * TSTRIDE + kt * 8 + t;
                bf[n][0] = Bb[base];
                bf[n][1] = Bb[base + 4];
            }
#pragma unroll
            for (int m = 0; m < 4; m++)
#pragma unroll
                for (int n = 0; n < 4; n++) MMA8(acc[m][n], af[m], bf[n]);
        }
    };

    const int KC = nc * 64;
    LDGA(0); STSA(0, 0);
    CPB(0, 0); CP_COMMIT(); CP_WAIT0();
    __syncthreads();
    for (int kc = 0; kc < KC; kc++) {
        const int s = kc & 1;
        const bool more = (kc + 1 < KC);
        if (more) LDGA(kc + 1);
        COMPUTE(s);
        if (more) {
            __syncthreads();
            CPB(kc + 1, s ^ 1); CP_COMMIT();
            STSA(kc + 1, s ^ 1);
            CP_WAIT0();
            __syncthreads();
        }
    }

    float* outt = p.out + (size_t)tk * Bn * On;
#pragma unroll
    for (int m = 0; m < 4; m++) {
        const int row = row0 + warp_m * 64 + m * 16 + g;
#pragma unroll
        for (int n = 0; n < 4; n++) {
            const int cl = warp_n * 32 + n * 8 + 2 * t;
            const float b0 = bsum[cl], b1 = bsum[cl + 1];
            float2 v;
            v.x = acc[m][n][0] + b0;
            v.y = acc[m][n][1] + b1;
            *(float2*)(outt + (size_t)row * On + n0 + cl) = v;
            v.x = acc[m][n][2] + b0;
            v.y = acc[m][n][3] + b1;
            *(float2*)(outt + (size_t)(row + 8) * On + n0 + cl) = v;
        }
    }
}

// ===================== Host launch =====================
extern "C" void kernel_launch(void* const* d_in, const int* in_sizes, int n_in,
                              void* d_out, int out_size) {
    P p;
    for (int i = 0; i < 8; i++) p.x[i] = (const float*)d_in[i];
    p.W_task  = (const float*)d_in[8];
    p.b_task  = (const float*)d_in[9];
    p.Wg_task = (const float*)d_in[10];
    p.bg_task = (const float*)d_in[11];
    p.Wo_task = (const float*)d_in[12];
    p.bo_task = (const float*)d_in[13];
    p.W_b2    = (const float*)d_in[14];
    p.b_b2    = (const float*)d_in[15];
    p.Wg_b2   = (const float*)d_in[16];
    p.bg_b2   = (const float*)d_in[17];
    p.Wo_b2   = (const float*)d_in[18];
    p.bo_b2   = (const float*)d_in[19];
    p.W_b3    = (const float*)d_in[20];
    p.b_b3    = (const float*)d_in[21];
    p.Wg_b3   = (const float*)d_in[22];
    p.bg_b3   = (const float*)d_in[23];
    p.Wo_b3   = (const float*)d_in[24];
    p.bo_b3   = (const float*)d_in[25];
    p.out = (float*)d_out;

    cudaFuncSetAttribute(k_hidden_mma, cudaFuncAttributeMaxDynamicSharedMemorySize, SMEM_DYN_BYTES);
    cudaFuncSetAttribute(k_out_mma,    cudaFuncAttributeMaxDynamicSharedMemorySize, SMEM_DYN_BYTES);

    // Transpose + tf32-round all weights into g_wt
    k_tr<<<dim3(2048 / 32, 256 / 32, 8), dim3(32, 8)>>>(p.W_task, WT_TASK, 256, 2048);
    k_tr<<<dim3(2048 / 32, 512 / 32, 4), dim3(32, 8)>>>(p.W_b2,   WT_B2,   512, 2048);
    k_tr<<<dim3(2048 / 32, 768 / 32, 6), dim3(32, 8)>>>(p.W_b3,   WT_B3,   768, 2048);
    k_tr<<<dim3(256 / 32, 2048 / 32, 8), dim3(32, 8)>>>(p.Wo_task, WOT,                           2048, 256);
    k_tr<<<dim3(256 / 32, 2048 / 32, 4), dim3(32, 8)>>>(p.Wo_b2,   WOT + (size_t)8  * 256 * 2048, 2048, 256);
    k_tr<<<dim3(256 / 32, 2048 / 32, 6), dim3(32, 8)>>>(p.Wo_b3,   WOT + (size_t)12 * 256 * 2048, 2048, 256);

    k_hidden_mma<<<dim3(Hn / 128, Bn / 128, 18), 256, SMEM_DYN_BYTES>>>(p);
    k_gate<<<dim3(Bn, 18), 128>>>(p);
    k_out_mma<<<dim3(On / 128, Bn / 128, 8), 256, SMEM_DYN_BYTES>>>(p);
}

// round 6
// speedup vs baseline: 3.4267x; 1.3380x over previous
#include <cuda_runtime.h>
#include <cuda_fp16.h>
#include <cstdint>
#include <cstddef>

// Problem dims
#define Bn 4096
#define Dn 256
#define Hn 2048
#define On 256

static constexpr size_t BH      = (size_t)Bn * Hn;
static constexpr size_t SE2_OFF = (size_t)8 * Bn * On;
static constexpr size_t SE3_OFF = SE2_OFF + (size_t)4 * BH;

// Scratch (.bss — no allocation)
__device__ float g_te[(size_t)8 * BH];       // per-task hidden fp32
__device__ float g_gate[18 * Bn];

// Transposed fp16 weights: [N,K] K-major rows
static constexpr size_t WT_TASK = 0;                                   // 8  x [2048 x 256]
static constexpr size_t WT_B2   = (size_t)8 * 2048 * 256;              // 4  x [2048 x 512]
static constexpr size_t WT_B3   = WT_B2 + (size_t)4 * 2048 * 512;      // 6  x [2048 x 768]
static constexpr size_t WOT     = WT_B3 + (size_t)6 * 2048 * 768;      // 18 x [256 x 2048]
__device__ __half g_wt[WOT + (size_t)18 * 256 * 2048];

// Routing
__constant__ int c_cnt[8]    = {1, 3, 2, 2, 4, 2, 2, 2};
__constant__ int c_lst[8][4] = {
    {0,0,0,0},{1,8,9,0},{2,10,0,0},{3,11,0,0},
    {4,12,13,14},{5,15,0,0},{6,16,0,0},{7,17,0,0}
};

struct P {
    const float* x[8];
    const float* W_task; const float* b_task; const float* Wg_task; const float* bg_task;
    const float* Wo_task; const float* bo_task;
    const float* W_b2;  const float* b_b2;  const float* Wg_b2;  const float* bg_b2;
    const float* Wo_b2; const float* bo_b2;
    const float* W_b3;  const float* b_b3;  const float* Wg_b3;  const float* bg_b3;
    const float* Wo_b3; const float* bo_b3;
    float* out;
};

// ===================== helpers =====================
__device__ __forceinline__ uint32_t smem_u32(const void* p) {
    uint32_t a;
    asm("{ .reg .u64 t; cvta.to.shared.u64 t, %1; cvt.u32.u64 %0, t; }" : "=r"(a) : "l"(p));
    return a;
}
__device__ __forceinline__ uint32_t pack2(float a, float b) {
    __half2 h = __floats2half2_rn(a, b);
    return *(uint32_t*)&h;
}
#define CP_ASYNC16(dst_u32, src_gptr) \
    asm volatile("cp.async.cg.shared.global [%0], [%1], 16;" :: "r"(dst_u32), "l"(src_gptr))
#define CP_COMMIT() asm volatile("cp.async.commit_group;" ::: "memory")
#define CP_WAIT0()  asm volatile("cp.async.wait_group 0;"  ::: "memory")

#define LDSM4(r0, r1, r2, r3, addr) \
    asm volatile("ldmatrix.sync.aligned.m8n8.x4.shared.b16 {%0,%1,%2,%3}, [%4];" \
                 : "=r"(r0), "=r"(r1), "=r"(r2), "=r"(r3) : "r"(addr))

#define MMA16(d, a, b) \
    asm volatile("mma.sync.aligned.m16n8k16.row.col.f32.f16.f16.f32 " \
                 "{%0,%1,%2,%3}, {%4,%5,%6,%7}, {%8,%9}, {%0,%1,%2,%3};" \
                 : "+f"((d)[0]), "+f"((d)[1]), "+f"((d)[2]), "+f"((d)[3]) \
                 : "r"((a)[0]), "r"((a)[1]), "r"((a)[2]), "r"((a)[3]), \
                   "r"((b)[0]), "r"((b)[1]))

// Smem tiles: 32 k-cols padded to 40 halves per row (80 B) → conflict-free ldmatrix
#define TST 40

// ===================== Kernel 0: weight transpose + fp16 convert =====================
__global__ __launch_bounds__(256) void k_tr(const float* in, size_t off, int R, int C) {
    __shared__ float tile[32][33];
    const int z = blockIdx.z;
    const float* inz = in + (size_t)z * R * C;
    __half* outz = g_wt + off + (size_t)z * R * C;
    const int rb = blockIdx.y * 32, cb = blockIdx.x * 32;
    const int tx = threadIdx.x, ty = threadIdx.y;
#pragma unroll
    for (int i = ty; i < 32; i += 8)
        tile[i][tx] = inz[(size_t)(rb + i) * C + cb + tx];
    __syncthreads();
#pragma unroll
    for (int i = ty; i < 32; i += 8)
        outz[(size_t)(cb + i) * R + rb + tx] = __float2half_rn(tile[tx][i]);
}

// ===================== Kernel 1: hidden = relu(X_e @ W_e + b_e) =====================
// grid (Hn/128, Bn/128, 18), 256 threads; CTA 128x128x32, warp 64x32 (2x4 warps)
__global__ __launch_bounds__(256, 2) void k_hidden_mma(P p) {
    extern __shared__ __half sm[];
    __half* As[2] = { sm,               sm + 128 * TST };
    __half* Bs[2] = { sm + 2 * 128 * TST, sm + 3 * 128 * TST };

    const int tid = threadIdx.x, wid = tid >> 5, lane = tid & 31;
    const int warp_m = wid >> 2, warp_n = wid & 3;
    const int g = lane >> 2, t = lane & 3;
    const int e = blockIdx.z;
    const int row0 = blockIdx.y * 128, n0 = blockIdx.x * 128;

    const float *xp0, *xp1 = nullptr, *xp2 = nullptr, *bias;
    const __half* wt; int K; float* dst;
    if (e < 8) {
        K = 256; xp0 = p.x[e];
        wt = g_wt + WT_TASK + (size_t)e * Hn * 256;
        bias = p.b_task + e * Hn;
        dst = g_te + (size_t)e * BH;
    } else if (e < 12) {
        const int q = e - 8;
        K = 512; xp0 = p.x[2]; xp1 = p.x[3];
        wt = g_wt + WT_B2 + (size_t)q * Hn * 512;
        bias = p.b_b2 + q * Hn;
        dst = p.out + SE2_OFF + (size_t)q * BH;
    } else {
        const int q = e - 12;
        K = 768; xp0 = p.x[5]; xp1 = p.x[6]; xp2 = p.x[7];
        wt = g_wt + WT_B3 + (size_t)q * Hn * 768;
        bias = p.b_b3 + q * Hn;
        dst = p.out + SE3_OFF + (size_t)q * BH;
    }

    const int arow = tid >> 1, acg = (tid & 1) * 2;   // A staging: row, col-group base
    float acc[4][4][4];
#pragma unroll
    for (int m = 0; m < 4; m++)
#pragma unroll
        for (int n = 0; n < 4; n++)
#pragma unroll
            for (int r = 0; r < 4; r++) acc[m][n][r] = 0.f;

    float4 pa[2][2];
    auto LDGA = [&](int kc) {
        const int kcol = kc * 32;
        const int part = kcol >> 8, kloc = kcol & 255;
        const float* xa = (part == 0) ? xp0 : ((part == 1) ? xp1 : xp2);
        const float* rp = xa + (size_t)(row0 + arow) * Dn + kloc;
#pragma unroll
        for (int i = 0; i < 2; i++) {
            const int c0 = (acg + i) * 8;
            pa[i][0] = *(const float4*)(rp + c0);
            pa[i][1] = *(const float4*)(rp + c0 + 4);
        }
    };
    auto STSA = [&](int s) {
        __half* ab = As[s];
#pragma unroll
        for (int i = 0; i < 2; i++) {
            uint4 w;
            w.x = pack2(pa[i][0].x, pa[i][0].y);
            w.y = pack2(pa[i][0].z, pa[i][0].w);
            w.z = pack2(pa[i][1].x, pa[i][1].y);
            w.w = pack2(pa[i][1].z, pa[i][1].w);
            *(uint4*)(ab + arow * TST + (acg + i) * 8) = w;
        }
    };
    auto CPB = [&](int kc, int s) {
        const int kcol = kc * 32;
        const uint32_t bb = smem_u32(Bs[s]);
#pragma unroll
        for (int i = 0; i < 2; i++) {
            const __half* src = wt + (size_t)(n0 + arow) * K + kcol + (acg + i) * 8;
            CP_ASYNC16(bb + (arow * TST + (acg + i) * 8) * 2, src);
        }
    };
    auto COMPUTE = [&](int s) {
        const uint32_t ab = smem_u32(As[s]);
        const uint32_t bb = smem_u32(Bs[s]);
#pragma unroll
        for (int kt = 0; kt < 2; kt++) {
            uint32_t af[4][4], bf[4][2];
#pragma unroll
            for (int m = 0; m < 4; m++) {
                const uint32_t addr = ab + (((warp_m * 64 + m * 16 + (lane & 15)) * TST)
                                            + kt * 16 + (lane >> 4) * 8) * 2;
                LDSM4(af[m][0], af[m][1], af[m][2], af[m][3], addr);
            }
#pragma unroll
            for (int nb = 0; nb < 2; nb++) {
                uint32_t r0, r1, r2, r3;
                const uint32_t addr = bb + (((warp_n * 32 + nb * 16 + (lane & 7) + ((lane >> 3) & 1) * 8) * TST)
                                            + kt * 16 + (lane >> 4) * 8) * 2;
                LDSM4(r0, r1, r2, r3, addr);
                bf[nb * 2][0] = r0;     bf[nb * 2][1] = r2;
                bf[nb * 2 + 1][0] = r1; bf[nb * 2 + 1][1] = r3;
            }
#pragma unroll
            for (int m = 0; m < 4; m++)
#pragma unroll
                for (int n = 0; n < 4; n++) MMA16(acc[m][n], af[m], bf[n]);
        }
    };

    const int KC = K / 32;
    LDGA(0); STSA(0);
    CPB(0, 0); CP_COMMIT(); CP_WAIT0();
    __syncthreads();
    for (int kc = 0; kc < KC; kc++) {
        const int s = kc & 1;
        const bool more = (kc + 1 < KC);
        if (more) LDGA(kc + 1);
        COMPUTE(s);
        if (more) {
            __syncthreads();
            CPB(kc + 1, s ^ 1); CP_COMMIT();
            STSA(s ^ 1);
            CP_WAIT0();
            __syncthreads();
        }
    }

    // epilogue: bias + relu
#pragma unroll
    for (int m = 0; m < 4; m++) {
        const int row = row0 + warp_m * 64 + m * 16 + g;
#pragma unroll
        for (int n = 0; n < 4; n++) {
            const int col = n0 + warp_n * 32 + n * 8 + 2 * t;
            const float b0 = bias[col], b1 = bias[col + 1];
            float2 v;
            v.x = fmaxf(acc[m][n][0] + b0, 0.f);
            v.y = fmaxf(acc[m][n][1] + b1, 0.f);
            *(float2*)(dst + (size_t)row * Hn + col) = v;
            v.x = fmaxf(acc[m][n][2] + b0, 0.f);
            v.y = fmaxf(acc[m][n][3] + b1, 0.f);
            *(float2*)(dst + (size_t)(row + 8) * Hn + col) = v;
        }
    }
}

// ===================== Kernel 2: gates (SIMT) =====================
__global__ __launch_bounds__(128) void k_gate(P p) {
    const int e = blockIdx.y;
    const int row = blockIdx.x;
    const float* src; const float* wg; float bg; int K;
    if (e < 8) {
        src = p.x[e] + (size_t)row * Dn;
        wg = p.Wg_task + e * Dn; bg = p.bg_task[e]; K = Dn;
    } else if (e < 12) {
        const int q = e - 8;
        src = p.out + SE2_OFF + (size_t)q * BH + (size_t)row * Hn;
        wg = p.Wg_b2 + q * Hn; bg = p.bg_b2[q]; K = Hn;
    } else {
        const int q = e - 12;
        src = p.out + SE3_OFF + (size_t)q * BH + (size_t)row * Hn;
        wg = p.Wg_b3 + q * Hn; bg = p.bg_b3[q]; K = Hn;
    }
    float s = 0.f;
    for (int i = threadIdx.x; i < K; i += 128) s += src[i] * wg[i];
    __shared__ float red[128];
    red[threadIdx.x] = s;
    __syncthreads();
#pragma unroll
    for (int o = 64; o > 0; o >>= 1) {
        if (threadIdx.x < o) red[threadIdx.x] += red[threadIdx.x + o];
        __syncthreads();
    }
    if (threadIdx.x == 0)
        g_gate[e * Bn + row] = 1.f / (1.f + expf(-(red[0] + bg)));
}

// ===================== Kernel 3: task_out, routed accumulation =====================
// grid (Bn/128, 8), 256 threads; CTA 128x256x32, warp 64x64 (2x4 warps)
__global__ __launch_bounds__(256, 1) void k_out_mma(P p) {
    extern __shared__ __half sm[];
    __half* As[2] = { sm,                 sm + 128 * TST };
    __half* Bs[2] = { sm + 2 * 128 * TST, sm + 2 * 128 * TST + 256 * TST };
    __shared__ float gs[4][128];
    __shared__ float bsum[256];

    const int tid = threadIdx.x, wid = tid >> 5, lane = tid & 31;
    const int warp_m = wid >> 2, warp_n = wid & 3;
    const int g = lane >> 2, t = lane & 3;
    const int tk = blockIdx.y;
    const int row0 = blockIdx.x * 128;
    const int nc = c_cnt[tk];

    const float* hid[4]; const __half* wb[4];
    for (int ci = 0; ci < nc; ci++) {
        const int e = c_lst[tk][ci];
        hid[ci] = (e < 8) ? g_te + (size_t)e * BH
                : (e < 12) ? p.out + SE2_OFF + (size_t)(e - 8) * BH
                           : p.out + SE3_OFF + (size_t)(e - 12) * BH;
        wb[ci] = g_wt + WOT + (size_t)e * On * Hn;
    }
    {
        float s = 0.f;
        for (int ci = 0; ci < nc; ci++) {
            const int e = c_lst[tk][ci];
            if (tid < 128) gs[ci][tid] = g_gate[e * Bn + row0 + tid];
            const float* bo = (e < 8) ? (p.bo_task + e * On)
                             : (e < 12) ? (p.bo_b2 + (e - 8) * On)
                                        : (p.bo_b3 + (e - 12) * On);
            s += bo[tid];
        }
        bsum[tid] = s;
    }
    __syncthreads();

    const int arow = tid >> 1, acg = (tid & 1) * 2;
    float acc[4][8][4];
#pragma unroll
    for (int m = 0; m < 4; m++)
#pragma unroll
        for (int n = 0; n < 8; n++)
#pragma unroll
            for (int r = 0; r < 4; r++) acc[m][n][r] = 0.f;

    float4 pa[2][2];
    auto LDGA = [&](int kc) {
        const int ci = kc >> 6, kcol = (kc & 63) * 32;
        const float* rp = hid[ci] + (size_t)(row0 + arow) * Hn + kcol;
#pragma unroll
        for (int i = 0; i < 2; i++) {
            const int c0 = (acg + i) * 8;
            pa[i][0] = *(const float4*)(rp + c0);
            pa[i][1] = *(const float4*)(rp + c0 + 4);
        }
    };
    auto STSA = [&](int kc, int s) {
        const int ci = kc >> 6;
        const float gv = gs[ci][arow];
        __half* ab = As[s];
#pragma unroll
        for (int i = 0; i < 2; i++) {
            uint4 w;
            w.x = pack2(pa[i][0].x * gv, pa[i][0].y * gv);
            w.y = pack2(pa[i][0].z * gv, pa[i][0].w * gv);
            w.z = pack2(pa[i][1].x * gv, pa[i][1].y * gv);
            w.w = pack2(pa[i][1].z * gv, pa[i][1].w * gv);
            *(uint4*)(ab + arow * TST + (acg + i) * 8) = w;
        }
    };
    auto CPB = [&](int kc, int s) {
        const int ci = kc >> 6, kcol = (kc & 63) * 32;
        const uint32_t bb = smem_u32(Bs[s]);
#pragma unroll
        for (int it = 0; it < 4; it++) {
            const int item = tid + it * 256;          // 1024 items: row 0..255, cg 0..3
            const int r = item >> 2, cg = item & 3;
            const __half* src = wb[ci] + (size_t)r * Hn + kcol + cg * 8;
            CP_ASYNC16(bb + (r * TST + cg * 8) * 2, src);
        }
    };
    auto COMPUTE = [&](int s) {
        const uint32_t ab = smem_u32(As[s]);
        const uint32_t bb = smem_u32(Bs[s]);
#pragma unroll
        for (int kt = 0; kt < 2; kt++) {
            uint32_t af[4][4], bf[8][2];
#pragma unroll
            for (int m = 0; m < 4; m++) {
                const uint32_t addr = ab + (((warp_m * 64 + m * 16 + (lane & 15)) * TST)
                                            + kt * 16 + (lane >> 4) * 8) * 2;
                LDSM4(af[m][0], af[m][1], af[m][2], af[m][3], addr);
            }
#pragma unroll
            for (int nb = 0; nb < 4; nb++) {
                uint32_t r0, r1, r2, r3;
                const uint32_t addr = bb + (((warp_n * 64 + nb * 16 + (lane & 7) + ((lane >> 3) & 1) * 8) * TST)
                                            + kt * 16 + (lane >> 4) * 8) * 2;
                LDSM4(r0, r1, r2, r3, addr);
                bf[nb * 2][0] = r0;     bf[nb * 2][1] = r2;
                bf[nb * 2 + 1][0] = r1; bf[nb * 2 + 1][1] = r3;
            }
#pragma unroll
            for (int m = 0; m < 4; m++)
#pragma unroll
                for (int n = 0; n < 8; n++) MMA16(acc[m][n], af[m], bf[n]);
        }
    };

    const int KC = nc * 64;
    LDGA(0); STSA(0, 0);
    CPB(0, 0); CP_COMMIT(); CP_WAIT0();
    __syncthreads();
    for (int kc = 0; kc < KC; kc++) {
        const int s = kc & 1;
        const bool more = (kc + 1 < KC);
        if (more) LDGA(kc + 1);
        COMPUTE(s);
        if (more) {
            __syncthreads();
            CPB(kc + 1, s ^ 1); CP_COMMIT();
            STSA(kc + 1, s ^ 1);
            CP_WAIT0();
            __syncthreads();
        }
    }

    float* outt = p.out + (size_t)tk * Bn * On;
#pragma unroll
    for (int m = 0; m < 4; m++) {
        const int row = row0 + warp_m * 64 + m * 16 + g;
#pragma unroll
        for (int n = 0; n < 8; n++) {
            const int cl = warp_n * 64 + n * 8 + 2 * t;
            const float b0 = bsum[cl], b1 = bsum[cl + 1];
            float2 v;
            v.x = acc[m][n][0] + b0;
            v.y = acc[m][n][1] + b1;
            *(float2*)(outt + (size_t)row * On + cl) = v;
            v.x = acc[m][n][2] + b0;
            v.y = acc[m][n][3] + b1;
            *(float2*)(outt + (size_t)(row + 8) * On + cl) = v;
        }
    }
}

// ===================== Host launch =====================
extern "C" void kernel_launch(void* const* d_in, const int* in_sizes, int n_in,
                              void* d_out, int out_size) {
    P p;
    for (int i = 0; i < 8; i++) p.x[i] = (const float*)d_in[i];
    p.W_task  = (const float*)d_in[8];
    p.b_task  = (const float*)d_in[9];
    p.Wg_task = (const float*)d_in[10];
    p.bg_task = (const float*)d_in[11];
    p.Wo_task = (const float*)d_in[12];
    p.bo_task = (const float*)d_in[13];
    p.W_b2    = (const float*)d_in[14];
    p.b_b2    = (const float*)d_in[15];
    p.Wg_b2   = (const float*)d_in[16];
    p.bg_b2   = (const float*)d_in[17];
    p.Wo_b2   = (const float*)d_in[18];
    p.bo_b2   = (const float*)d_in[19];
    p.W_b3    = (const float*)d_in[20];
    p.b_b3    = (const float*)d_in[21];
    p.Wg_b3   = (const float*)d_in[22];
    p.bg_b3   = (const float*)d_in[23];
    p.Wo_b3   = (const float*)d_in[24];
    p.bo_b3   = (const float*)d_in[25];
    p.out = (float*)d_out;

    const int smh = 4 * 128 * TST * 2;                    // 40960 B
    const int smo = (2 * 128 * TST + 2 * 256 * TST) * 2;  // 61440 B
    cudaFuncSetAttribute(k_hidden_mma, cudaFuncAttributeMaxDynamicSharedMemorySize, smh);
    cudaFuncSetAttribute(k_out_mma,    cudaFuncAttributeMaxDynamicSharedMemorySize, smo);

    // Transpose + fp16-convert all weights into g_wt
    k_tr<<<dim3(2048 / 32, 256 / 32, 8), dim3(32, 8)>>>(p.W_task, WT_TASK, 256, 2048);
    k_tr<<<dim3(2048 / 32, 512 / 32, 4), dim3(32, 8)>>>(p.W_b2,   WT_B2,   512, 2048);
    k_tr<<<dim3(2048 / 32, 768 / 32, 6), dim3(32, 8)>>>(p.W_b3,   WT_B3,   768, 2048);
    k_tr<<<dim3(256 / 32, 2048 / 32, 8), dim3(32, 8)>>>(p.Wo_task, WOT,                           2048, 256);
    k_tr<<<dim3(256 / 32, 2048 / 32, 4), dim3(32, 8)>>>(p.Wo_b2,   WOT + (size_t)8  * 256 * 2048, 2048, 256);
    k_tr<<<dim3(256 / 32, 2048 / 32, 6), dim3(32, 8)>>>(p.Wo_b3,   WOT + (size_t)12 * 256 * 2048, 2048, 256);

    k_hidden_mma<<<dim3(Hn / 128, Bn / 128, 18), 256, smh>>>(p);
    k_gate<<<dim3(Bn, 18), 128>>>(p);
    k_out_mma<<<dim3(Bn / 128, 8), 256, smo>>>(p);
}

// round 7
// speedup vs baseline: 4.8961x; 1.4288x over previous
#include <cuda_runtime.h>
#include <cuda_fp16.h>
#include <cstdint>
#include <cstddef>

// Problem dims
#define Bn 4096
#define Dn 256
#define Hn 2048
#define On 256

static constexpr size_t BH      = (size_t)Bn * Hn;
static constexpr size_t SE2_OFF = (size_t)8 * Bn * On;
static constexpr size_t SE3_OFF = SE2_OFF + (size_t)4 * BH;

// Scratch (.bss — no allocation)
__device__ float g_te[(size_t)8 * BH];       // per-task hidden fp32
__device__ float g_gate[18 * Bn];
__device__ __half g_x16[(size_t)8 * Bn * Dn];  // fp16 copy of inputs

// Transposed fp16 weights: [N,K] K-major rows
static constexpr size_t WT_TASK = 0;                                   // 8  x [2048 x 256]
static constexpr size_t WT_B2   = (size_t)8 * 2048 * 256;              // 4  x [2048 x 512]
static constexpr size_t WT_B3   = WT_B2 + (size_t)4 * 2048 * 512;      // 6  x [2048 x 768]
static constexpr size_t WOT     = WT_B3 + (size_t)6 * 2048 * 768;      // 18 x [256 x 2048]
__device__ __half g_wt[WOT + (size_t)18 * 256 * 2048];

// Routing
__constant__ int c_cnt[8]    = {1, 3, 2, 2, 4, 2, 2, 2};
__constant__ int c_lst[8][4] = {
    {0,0,0,0},{1,8,9,0},{2,10,0,0},{3,11,0,0},
    {4,12,13,14},{5,15,0,0},{6,16,0,0},{7,17,0,0}
};
__constant__ int c_order[8] = {4, 1, 2, 3, 5, 6, 7, 0};  // heavy tasks first

struct P {
    const float* x[8];
    const float* W_task; const float* b_task; const float* Wg_task; const float* bg_task;
    const float* Wo_task; const float* bo_task;
    const float* W_b2;  const float* b_b2;  const float* Wg_b2;  const float* bg_b2;
    const float* Wo_b2; const float* bo_b2;
    const float* W_b3;  const float* b_b3;  const float* Wg_b3;  const float* bg_b3;
    const float* Wo_b3; const float* bo_b3;
    float* out;
};

// ===================== helpers =====================
__device__ __forceinline__ uint32_t smem_u32(const void* p) {
    uint32_t a;
    asm("{ .reg .u64 t; cvta.to.shared.u64 t, %1; cvt.u32.u64 %0, t; }" : "=r"(a) : "l"(p));
    return a;
}
__device__ __forceinline__ uint32_t pack2(float a, float b) {
    __half2 h = __floats2half2_rn(a, b);
    return *(uint32_t*)&h;
}
#define CP_ASYNC16(dst_u32, src_gptr) \
    asm volatile("cp.async.cg.shared.global [%0], [%1], 16;" :: "r"(dst_u32), "l"(src_gptr))
#define CP_COMMIT() asm volatile("cp.async.commit_group;" ::: "memory")
#define CP_WAIT0()  asm volatile("cp.async.wait_group 0;"  ::: "memory")

#define LDSM4(r0, r1, r2, r3, addr) \
    asm volatile("ldmatrix.sync.aligned.m8n8.x4.shared.b16 {%0,%1,%2,%3}, [%4];" \
                 : "=r"(r0), "=r"(r1), "=r"(r2), "=r"(r3) : "r"(addr))

#define MMA16(d, a, b) \
    asm volatile("mma.sync.aligned.m16n8k16.row.col.f32.f16.f16.f32 " \
                 "{%0,%1,%2,%3}, {%4,%5,%6,%7}, {%8,%9}, {%0,%1,%2,%3};" \
                 : "+f"((d)[0]), "+f"((d)[1]), "+f"((d)[2]), "+f"((d)[3]) \
                 : "r"((a)[0]), "r"((a)[1]), "r"((a)[2]), "r"((a)[3]), \
                   "r"((b)[0]), "r"((b)[1]))

// Smem tiles: 32 k-cols padded to 40 halves per row (80 B) → conflict-free ldmatrix
#define TST 40

// ===================== Kernel 0a: weight transpose + fp16 convert =====================
__global__ __launch_bounds__(256) void k_tr(const float* in, size_t off, int R, int C) {
    __shared__ float tile[32][33];
    const int z = blockIdx.z;
    const float* inz = in + (size_t)z * R * C;
    __half* outz = g_wt + off + (size_t)z * R * C;
    const int rb = blockIdx.y * 32, cb = blockIdx.x * 32;
    const int tx = threadIdx.x, ty = threadIdx.y;
#pragma unroll
    for (int i = ty; i < 32; i += 8)
        tile[i][tx] = inz[(size_t)(rb + i) * C + cb + tx];
    __syncthreads();
#pragma unroll
    for (int i = ty; i < 32; i += 8)
        outz[(size_t)(cb + i) * R + rb + tx] = __float2half_rn(tile[tx][i]);
}

// ===================== Kernel 0b: x -> fp16 =====================
__global__ __launch_bounds__(256) void k_x16(P p) {
    const size_t i = ((size_t)blockIdx.x * 256 + threadIdx.x) * 4;
    const size_t per = (size_t)Bn * Dn;
    const int e = (int)(i / per);
    const size_t off = i % per;
    const float4 v = *(const float4*)(p.x[e] + off);
    uint2 w;
    w.x = pack2(v.x, v.y);
    w.y = pack2(v.z, v.w);
    *(uint2*)(g_x16 + i) = w;
}

// ===================== Kernel 1: hidden = relu(X_e @ W_e + b_e) =====================
// grid (Hn/128, Bn/128, 18), 256 threads; CTA 128x128x32, warp 64x32 (2x4 warps)
// Both operands staged via cp.async (A from fp16 x copy), 2-stage overlapped pipeline.
__global__ __launch_bounds__(256, 2) void k_hidden_mma(P p) {
    extern __shared__ __half sm[];
    __half* As[2] = { sm,                 sm + 128 * TST };
    __half* Bs[2] = { sm + 2 * 128 * TST, sm + 3 * 128 * TST };

    const int tid = threadIdx.x, wid = tid >> 5, lane = tid & 31;
    const int warp_m = wid >> 2, warp_n = wid & 3;
    const int g = lane >> 2, t = lane & 3;
    const int e = blockIdx.z;
    const int row0 = blockIdx.y * 128, n0 = blockIdx.x * 128;

    const __half *xp0, *xp1 = nullptr, *xp2 = nullptr;
    const float* bias;
    const __half* wt; int K; float* dst;
    if (e < 8) {
        K = 256; xp0 = g_x16 + (size_t)e * Bn * Dn;
        wt = g_wt + WT_TASK + (size_t)e * Hn * 256;
        bias = p.b_task + e * Hn;
        dst = g_te + (size_t)e * BH;
    } else if (e < 12) {
        const int q = e - 8;
        K = 512;
        xp0 = g_x16 + (size_t)2 * Bn * Dn; xp1 = g_x16 + (size_t)3 * Bn * Dn;
        wt = g_wt + WT_B2 + (size_t)q * Hn * 512;
        bias = p.b_b2 + q * Hn;
        dst = p.out + SE2_OFF + (size_t)q * BH;
    } else {
        const int q = e - 12;
        K = 768;
        xp0 = g_x16 + (size_t)5 * Bn * Dn; xp1 = g_x16 + (size_t)6 * Bn * Dn;
        xp2 = g_x16 + (size_t)7 * Bn * Dn;
        wt = g_wt + WT_B3 + (size_t)q * Hn * 768;
        bias = p.b_b3 + q * Hn;
        dst = p.out + SE3_OFF + (size_t)q * BH;
    }

    float acc[4][4][4];
#pragma unroll
    for (int m = 0; m < 4; m++)
#pragma unroll
        for (int n = 0; n < 4; n++)
#pragma unroll
            for (int r = 0; r < 4; r++) acc[m][n][r] = 0.f;

    auto CPA = [&](int kc, int s) {
        const int kcol = kc * 32;
        const int part = kcol >> 8, kloc = kcol & 255;
        const __half* xa = (part == 0) ? xp0 : ((part == 1) ? xp1 : xp2);
        const uint32_t ab = smem_u32(As[s]);
#pragma unroll
        for (int it = 0; it < 2; it++) {
            const int item = tid + it * 256;         // 512 items: 128 rows x 4 col-groups
            const int r = item >> 2, cg = item & 3;
            const __half* src = xa + (size_t)(row0 + r) * Dn + kloc + cg * 8;
            CP_ASYNC16(ab + (r * TST + cg * 8) * 2, src);
        }
    };
    auto CPB = [&](int kc, int s) {
        const int kcol = kc * 32;
        const uint32_t bb = smem_u32(Bs[s]);
#pragma unroll
        for (int it = 0; it < 2; it++) {
            const int item = tid + it * 256;
            const int r = item >> 2, cg = item & 3;
            const __half* src = wt + (size_t)(n0 + r) * K + kcol + cg * 8;
            CP_ASYNC16(bb + (r * TST + cg * 8) * 2, src);
        }
    };
    auto COMPUTE = [&](int s) {
        const uint32_t ab = smem_u32(As[s]);
        const uint32_t bb = smem_u32(Bs[s]);
#pragma unroll
        for (int kt = 0; kt < 2; kt++) {
            uint32_t af[4][4], bf[4][2];
#pragma unroll
            for (int m = 0; m < 4; m++) {
                const uint32_t addr = ab + (((warp_m * 64 + m * 16 + (lane & 15)) * TST)
                                            + kt * 16 + (lane >> 4) * 8) * 2;
                LDSM4(af[m][0], af[m][1], af[m][2], af[m][3], addr);
            }
#pragma unroll
            for (int nb = 0; nb < 2; nb++) {
                uint32_t r0, r1, r2, r3;
                const uint32_t addr = bb + (((warp_n * 32 + nb * 16 + (lane & 7) + ((lane >> 3) & 1) * 8) * TST)
                                            + kt * 16 + (lane >> 4) * 8) * 2;
                LDSM4(r0, r1, r2, r3, addr);
                bf[nb * 2][0] = r0;     bf[nb * 2][1] = r2;
                bf[nb * 2 + 1][0] = r1; bf[nb * 2 + 1][1] = r3;
            }
#pragma unroll
            for (int m = 0; m < 4; m++)
#pragma unroll
                for (int n = 0; n < 4; n++) MMA16(acc[m][n], af[m], bf[n]);
        }
    };

    const int KC = K / 32;
    CPA(0, 0); CPB(0, 0); CP_COMMIT();
    CP_WAIT0();
    __syncthreads();
    for (int kc = 0; kc < KC; kc++) {
        const int s = kc & 1;
        const bool more = (kc + 1 < KC);
        if (more) { CPA(kc + 1, s ^ 1); CPB(kc + 1, s ^ 1); CP_COMMIT(); }
        COMPUTE(s);
        if (more) { CP_WAIT0(); __syncthreads(); }
    }

    // epilogue: bias + relu
#pragma unroll
    for (int m = 0; m < 4; m++) {
        const int row = row0 + warp_m * 64 + m * 16 + g;
#pragma unroll
        for (int n = 0; n < 4; n++) {
            const int col = n0 + warp_n * 32 + n * 8 + 2 * t;
            const float b0 = bias[col], b1 = bias[col + 1];
            float2 v;
            v.x = fmaxf(acc[m][n][0] + b0, 0.f);
            v.y = fmaxf(acc[m][n][1] + b1, 0.f);
            *(float2*)(dst + (size_t)row * Hn + col) = v;
            v.x = fmaxf(acc[m][n][2] + b0, 0.f);
            v.y = fmaxf(acc[m][n][3] + b1, 0.f);
            *(float2*)(dst + (size_t)(row + 8) * Hn + col) = v;
        }
    }
}

// ===================== Kernel 2: gates — one warp per (expert,row) =====================
__global__ __launch_bounds__(256) void k_gate(P p) {
    const int gw = blockIdx.x * 8 + (threadIdx.x >> 5);
    const int lane = threadIdx.x & 31;
    const int e = gw >> 12, row = gw & (Bn - 1);

    const float* src; const float* wg; float bg; int K;
    if (e < 8) {
        src = p.x[e] + (size_t)row * Dn;
        wg = p.Wg_task + e * Dn; bg = p.bg_task[e]; K = Dn;
    } else if (e < 12) {
        const int q = e - 8;
        src = p.out + SE2_OFF + (size_t)q * BH + (size_t)row * Hn;
        wg = p.Wg_b2 + q * Hn; bg = p.bg_b2[q]; K = Hn;
    } else {
        const int q = e - 12;
        src = p.out + SE3_OFF + (size_t)q * BH + (size_t)row * Hn;
        wg = p.Wg_b3 + q * Hn; bg = p.bg_b3[q]; K = Hn;
    }
    float s = 0.f;
    for (int i = lane * 4; i < K; i += 128) {
        const float4 v = *(const float4*)(src + i);
        const float4 w = *(const float4*)(wg + i);
        s += v.x * w.x + v.y * w.y + v.z * w.z + v.w * w.w;
    }
#pragma unroll
    for (int o = 16; o > 0; o >>= 1) s += __shfl_xor_sync(0xFFFFFFFFu, s, o);
    if (lane == 0)
        g_gate[e * Bn + row] = 1.f / (1.f + expf(-(s + bg)));
}

// ===================== Kernel 3: task_out, routed accumulation =====================
// grid (Bn/128, 8), 256 threads; CTA 128x256x32, warp 64x64 (2x4 warps)
__global__ __launch_bounds__(256, 1) void k_out_mma(P p) {
    extern __shared__ __half sm[];
    __half* As[2] = { sm,                 sm + 128 * TST };
    __half* Bs[2] = { sm + 2 * 128 * TST, sm + 2 * 128 * TST + 256 * TST };
    __shared__ float gs[4][128];
    __shared__ float bsum[256];

    const int tid = threadIdx.x, wid = tid >> 5, lane = tid & 31;
    const int warp_m = wid >> 2, warp_n = wid & 3;
    const int g = lane >> 2, t = lane & 3;
    const int tk = c_order[blockIdx.y];
    const int row0 = blockIdx.x * 128;
    const int nc = c_cnt[tk];

    const float* hid[4]; const __half* wb[4];
    for (int ci = 0; ci < nc; ci++) {
        const int e = c_lst[tk][ci];
        hid[ci] = (e < 8) ? g_te + (size_t)e * BH
                : (e < 12) ? p.out + SE2_OFF + (size_t)(e - 8) * BH
                           : p.out + SE3_OFF + (size_t)(e - 12) * BH;
        wb[ci] = g_wt + WOT + (size_t)e * On * Hn;
    }
    {
        float s = 0.f;
        for (int ci = 0; ci < nc; ci++) {
            const int e = c_lst[tk][ci];
            if (tid < 128) gs[ci][tid] = g_gate[e * Bn + row0 + tid];
            const float* bo = (e < 8) ? (p.bo_task + e * On)
                             : (e < 12) ? (p.bo_b2 + (e - 8) * On)
                                        : (p.bo_b3 + (e - 12) * On);
            s += bo[tid];
        }
        bsum[tid] = s;
    }
    __syncthreads();

    const int arow = tid >> 1, acg = (tid & 1) * 2;
    float acc[4][8][4];
#pragma unroll
    for (int m = 0; m < 4; m++)
#pragma unroll
        for (int n = 0; n < 8; n++)
#pragma unroll
            for (int r = 0; r < 4; r++) acc[m][n][r] = 0.f;

    float4 pa[2][2];
    auto LDGA = [&](int kc) {
        const int ci = kc >> 6, kcol = (kc & 63) * 32;
        const float* rp = hid[ci] + (size_t)(row0 + arow) * Hn + kcol;
#pragma unroll
        for (int i = 0; i < 2; i++) {
            const int c0 = (acg + i) * 8;
            pa[i][0] = *(const float4*)(rp + c0);
            pa[i][1] = *(const float4*)(rp + c0 + 4);
        }
    };
    auto STSA = [&](int kc, int s) {
        const int ci = kc >> 6;
        const float gv = gs[ci][arow];
        __half* ab = As[s];
#pragma unroll
        for (int i = 0; i < 2; i++) {
            uint4 w;
            w.x = pack2(pa[i][0].x * gv, pa[i][0].y * gv);
            w.y = pack2(pa[i][0].z * gv, pa[i][0].w * gv);
            w.z = pack2(pa[i][1].x * gv, pa[i][1].y * gv);
            w.w = pack2(pa[i][1].z * gv, pa[i][1].w * gv);
            *(uint4*)(ab + arow * TST + (acg + i) * 8) = w;
        }
    };
    auto CPB = [&](int kc, int s) {
        const int ci = kc >> 6, kcol = (kc & 63) * 32;
        const uint32_t bb = smem_u32(Bs[s]);
#pragma unroll
        for (int it = 0; it < 4; it++) {
            const int item = tid + it * 256;          // 1024 items: 256 rows x 4 col-groups
            const int r = item >> 2, cg = item & 3;
            const __half* src = wb[ci] + (size_t)r * Hn + kcol + cg * 8;
            CP_ASYNC16(bb + (r * TST + cg * 8) * 2, src);
        }
    };
    auto COMPUTE = [&](int s) {
        const uint32_t ab = smem_u32(As[s]);
        const uint32_t bb = smem_u32(Bs[s]);
#pragma unroll
        for (int kt = 0; kt < 2; kt++) {
            uint32_t af[4][4], bf[8][2];
#pragma unroll
            for (int m = 0; m < 4; m++) {
                const uint32_t addr = ab + (((warp_m * 64 + m * 16 + (lane & 15)) * TST)
                                            + kt * 16 + (lane >> 4) * 8) * 2;
                LDSM4(af[m][0], af[m][1], af[m][2], af[m][3], addr);
            }
#pragma unroll
            for (int nb = 0; nb < 4; nb++) {
                uint32_t r0, r1, r2, r3;
                const uint32_t addr = bb + (((warp_n * 64 + nb * 16 + (lane & 7) + ((lane >> 3) & 1) * 8) * TST)
                                            + kt * 16 + (lane >> 4) * 8) * 2;
                LDSM4(r0, r1, r2, r3, addr);
                bf[nb * 2][0] = r0;     bf[nb * 2][1] = r2;
                bf[nb * 2 + 1][0] = r1; bf[nb * 2 + 1][1] = r3;
            }
#pragma unroll
            for (int m = 0; m < 4; m++)
#pragma unroll
                for (int n = 0; n < 8; n++) MMA16(acc[m][n], af[m], bf[n]);
        }
    };

    const int KC = nc * 64;
    // prologue
    LDGA(0); CPB(0, 0); CP_COMMIT(); STSA(0, 0);
    CP_WAIT0();
    __syncthreads();
    for (int kc = 0; kc < KC; kc++) {
        const int s = kc & 1;
        const bool more = (kc + 1 < KC);
        if (more) { LDGA(kc + 1); CPB(kc + 1, s ^ 1); CP_COMMIT(); }
        COMPUTE(s);
        if (more) { STSA(kc + 1, s ^ 1); CP_WAIT0(); __syncthreads(); }
    }

    float* outt = p.out + (size_t)tk * Bn * On;
#pragma unroll
    for (int m = 0; m < 4; m++) {
        const int row = row0 + warp_m * 64 + m * 16 + g;
#pragma unroll
        for (int n = 0; n < 8; n++) {
            const int cl = warp_n * 64 + n * 8 + 2 * t;
            const float b0 = bsum[cl], b1 = bsum[cl + 1];
            float2 v;
            v.x = acc[m][n][0] + b0;
            v.y = acc[m][n][1] + b1;
            *(float2*)(outt + (size_t)row * On + cl) = v;
            v.x = acc[m][n][2] + b0;
            v.y = acc[m][n][3] + b1;
            *(float2*)(outt + (size_t)(row + 8) * On + cl) = v;
        }
    }
}

// ===================== Host launch =====================
extern "C" void kernel_launch(void* const* d_in, const int* in_sizes, int n_in,
                              void* d_out, int out_size) {
    P p;
    for (int i = 0; i < 8; i++) p.x[i] = (const float*)d_in[i];
    p.W_task  = (const float*)d_in[8];
    p.b_task  = (const float*)d_in[9];
    p.Wg_task = (const float*)d_in[10];
    p.bg_task = (const float*)d_in[11];
    p.Wo_task = (const float*)d_in[12];
    p.bo_task = (const float*)d_in[13];
    p.W_b2    = (const float*)d_in[14];
    p.b_b2    = (const float*)d_in[15];
    p.Wg_b2   = (const float*)d_in[16];
    p.bg_b2   = (const float*)d_in[17];
    p.Wo_b2   = (const float*)d_in[18];
    p.bo_b2   = (const float*)d_in[19];
    p.W_b3    = (const float*)d_in[20];
    p.b_b3    = (const float*)d_in[21];
    p.Wg_b3   = (const float*)d_in[22];
    p.bg_b3   = (const float*)d_in[23];
    p.Wo_b3   = (const float*)d_in[24];
    p.bo_b3   = (const float*)d_in[25];
    p.out = (float*)d_out;

    const int smh = 4 * 128 * TST * 2;                    // 40960 B
    const int smo = (2 * 128 * TST + 2 * 256 * TST) * 2;  // 61440 B
    cudaFuncSetAttribute(k_hidden_mma, cudaFuncAttributeMaxDynamicSharedMemorySize, smh);
    cudaFuncSetAttribute(k_out_mma,    cudaFuncAttributeMaxDynamicSharedMemorySize, smo);

    // Prep: weights transpose+fp16, x fp16 copy
    k_tr<<<dim3(2048 / 32, 256 / 32, 8), dim3(32, 8)>>>(p.W_task, WT_TASK, 256, 2048);
    k_tr<<<dim3(2048 / 32, 512 / 32, 4), dim3(32, 8)>>>(p.W_b2,   WT_B2,   512, 2048);
    k_tr<<<dim3(2048 / 32, 768 / 32, 6), dim3(32, 8)>>>(p.W_b3,   WT_B3,   768, 2048);
    k_tr<<<dim3(256 / 32, 2048 / 32, 8), dim3(32, 8)>>>(p.Wo_task, WOT,                           2048, 256);
    k_tr<<<dim3(256 / 32, 2048 / 32, 4), dim3(32, 8)>>>(p.Wo_b2,   WOT + (size_t)8  * 256 * 2048, 2048, 256);
    k_tr<<<dim3(256 / 32, 2048 / 32, 6), dim3(32, 8)>>>(p.Wo_b3,   WOT + (size_t)12 * 256 * 2048, 2048, 256);
    k_x16<<<(int)(((size_t)8 * Bn * Dn / 4) / 256), 256>>>(p);

    k_hidden_mma<<<dim3(Hn / 128, Bn / 128, 18), 256, smh>>>(p);
    k_gate<<<dim3(18 * Bn / 8), 256>>>(p);
    k_out_mma<<<dim3(Bn / 128, 8), 256, smo>>>(p);
}